// round 11
// baseline (speedup 1.0000x reference)
#include <cuda_runtime.h>
#include <cuda_bf16.h>
#include <cstdint>

#define Bq 8
#define Nn 2048
#define Dd 128
#define TM 128
#define TK 32
#define NS 3
#define KSPLIT 2
#define NTHR 512
#define NBLK (Bq * (Nn / TM) * KSPLIT)   // 256

// smem strides (bytes), conflict-free for fragment LDS patterns
#define A_STRIDE 160      // 128B fp32 data + 32B pad (40 words)
#define B_STRIDE 80       // 64B bf16 data + 16B pad (20 words)
#define A_STAGE  (TM * A_STRIDE)          // 20480
#define B_BYTES  (Dd * B_STRIDE)          // 10240
#define HS_OFF   (A_STAGE + B_BYTES)      // 30720
#define STAGE_BYTES (HS_OFF + 128)        // 30848
#define SMEM_BYTES  (NS * STAGE_BYTES)    // 92544

// scratch (no allocation allowed -> device globals)
__device__ float          g_hsq[Bq * Nn];
__device__ __nv_bfloat16  g_Bt[(size_t)Bq * Dd * Nn];   // [b][d][j] bf16
__device__ float          g_part[NBLK];
__device__ int            g_done;

__device__ __forceinline__ uint32_t smem_u32(const void* p) {
    uint32_t a;
    asm("{ .reg .u64 t; cvta.to.shared.u64 t, %1; cvt.u32.u64 %0, t; }"
        : "=r"(a) : "l"(p));
    return a;
}
__device__ __forceinline__ void cp16(uint32_t dst, const void* src) {
    asm volatile("cp.async.cg.shared.global [%0], [%1], 16;"
                 :: "r"(dst), "l"(src) : "memory");
}
__device__ __forceinline__ uint32_t packbf(float x, float y) {
    __nv_bfloat162 p = __floats2bfloat162_rn(x, y);
    return *reinterpret_cast<uint32_t*>(&p);
}

// ---------------------------------------------------------------------------
// Kernel 0 (prep, conflict-free): hsq + bf16 transposed embedding Bt[b][d][j]
// ---------------------------------------------------------------------------
__global__ void k_prep(const float* __restrict__ H) {
    __shared__ float s2[32][137];   // odd stride -> conflict-free column reads
    __shared__ float hq[32];
    const int b = blockIdx.y, j0 = blockIdx.x * 32;
    const int tid = threadIdx.x;    // 256
    if (blockIdx.x == 0 && blockIdx.y == 0 && tid == 0) g_done = 0;

    #pragma unroll
    for (int c = 0; c < 4; c++) {
        int idx = tid + c * 256;            // 1024 float4s
        int j = idx >> 5, d4 = (idx & 31) * 4;
        float4 v = *(const float4*)(H + ((size_t)(b * Nn + j0 + j)) * Dd + d4);
        s2[j][d4 + 0] = v.x; s2[j][d4 + 1] = v.y;
        s2[j][d4 + 2] = v.z; s2[j][d4 + 3] = v.w;
    }
    __syncthreads();

    {   // hsq: warp w -> 4 rows, 8 lanes per row
        const int w = tid >> 5, l = tid & 31;
        const int j = w * 4 + (l >> 3), sub = l & 7;
        float sum = 0.f;
        #pragma unroll
        for (int m = 0; m < 16; m++) {
            float v = s2[j][sub + 8 * m];
            sum += v * v;
        }
        sum += __shfl_xor_sync(0xFFFFFFFFu, sum, 1);
        sum += __shfl_xor_sync(0xFFFFFFFFu, sum, 2);
        sum += __shfl_xor_sync(0xFFFFFFFFu, sum, 4);
        if (sub == 0) { hq[j] = sum; g_hsq[b * Nn + j0 + j] = sum; }
    }
    __syncthreads();

    for (int idx = tid; idx < Dd * 8; idx += 256) {
        int d = idx >> 3, jq = (idx & 7) * 4;
        uint2 p;
        p.x = packbf(s2[jq + 0][d], s2[jq + 1][d]);
        p.y = packbf(s2[jq + 2][d], s2[jq + 3][d]);
        *(uint2*)&g_Bt[((size_t)(b * Dd + d)) * Nn + j0 + jq] = p;
    }
}

// ---------------------------------------------------------------------------
// Kernel 1: 512-thread bf16 GEMM, warps 4(m) x 4(n), warp tile m32 x n32.
// Same 128-row tile & NS=3 issue-before-wait pipeline as R9. Side terms
// (row-sums, hsq-weighted col-sums) in fp32 from A fragments (R7-proven).
// Fused epilogue + last-CTA deterministic reduction.
// ---------------------------------------------------------------------------
__global__ __launch_bounds__(NTHR, 2)
void k_main(const float* __restrict__ A, const float* __restrict__ H,
            float* __restrict__ out) {
    extern __shared__ char smem[];
    __shared__ float s_red[16];
    __shared__ int   s_last;
    const uint32_t sb0 = smem_u32(smem);
    const int tid = threadIdx.x;
    const int wid = tid >> 5, lane = tid & 31;
    const int ks = blockIdx.x, mt = blockIdx.y, b = blockIdx.z;
    const int i0 = mt * TM;
    const int kbase = ks * (Nn / KSPLIT);
    const int NIT = (Nn / KSPLIT) / TK;         // 32

    const int wm = wid >> 2;          // 0..3 -> m offset 32*wm
    const int wn = wid & 3;           // 0..3 -> n cols [32*wn, 32*wn+32)
    const int qr = lane >> 2;         // 0..7
    const int qc = (lane & 3) * 2;    // 0,2,4,6

    const float*         Ag = A + ((size_t)b * Nn + i0) * Nn + kbase;
    const __nv_bfloat16* Bg = g_Bt + ((size_t)b * Dd) * Nn + kbase;
    const float*         Hg = g_hsq + b * Nn + kbase;

    float acc[2][4][4];
    #pragma unroll
    for (int f = 0; f < 2; f++)
        #pragma unroll
        for (int t = 0; t < 4; t++)
            #pragma unroll
            for (int r = 0; r < 4; r++) acc[f][t][r] = 0.f;
    float rs[2][2] = {{0.f, 0.f}, {0.f, 0.f}};
    float cs = 0.f;

    auto issue = [&](int s, int it) {
        uint32_t sa = sb0 + s * STAGE_BYTES;
        const float* ag = Ag + it * TK;
        #pragma unroll
        for (int c = 0; c < 2; c++) {
            int e = tid + c * NTHR;                // 1024 chunks (A)
            int row = e >> 3, ch = e & 7;
            cp16(sa + row * A_STRIDE + ch * 16, ag + (size_t)row * Nn + ch * 4);
        }
        {   // B: 128 rows x 4 chunks = 512 = NTHR
            int row = tid >> 2, ch = tid & 3;
            cp16(sa + A_STAGE + row * B_STRIDE + ch * 16,
                 Bg + it * TK + (size_t)row * Nn + ch * 8);
        }
        if (tid < 8)   // hsq k-slice: 32 floats = 128B
            cp16(sa + HS_OFF + tid * 16, Hg + it * TK + tid * 4);
    };

    // prologue
    #pragma unroll
    for (int p = 0; p < NS - 1; p++) {
        issue(p, p);
        asm volatile("cp.async.commit_group;" ::: "memory");
    }

    for (int it = 0; it < NIT; it++) {
        const int pre = it + NS - 1;
        if (pre < NIT) issue(pre % NS, pre);
        asm volatile("cp.async.commit_group;" ::: "memory");
        asm volatile("cp.async.wait_group %0;" :: "n"(NS - 1) : "memory");
        __syncthreads();

        const char* smA = smem + (it % NS) * STAGE_BYTES;
        const char* smB = smA + A_STAGE;
        const float* smH = (const float*)(smA + HS_OFF);

        #pragma unroll
        for (int k16 = 0; k16 < TK; k16 += 16) {
            uint32_t a[2][4];
            #pragma unroll
            for (int f = 0; f < 2; f++) {
                const char* ap = smA + (wm * 32 + f * 16 + qr) * A_STRIDE;
                float2 v00 = *(const float2*)(ap + (k16 + qc) * 4);
                float2 v10 = *(const float2*)(ap + 8 * A_STRIDE + (k16 + qc) * 4);
                float2 v01 = *(const float2*)(ap + (k16 + qc + 8) * 4);
                float2 v11 = *(const float2*)(ap + 8 * A_STRIDE + (k16 + qc + 8) * 4);
                if (wn == 0) {
                    rs[f][0] += v00.x + v00.y + v01.x + v01.y;
                    rs[f][1] += v10.x + v10.y + v11.x + v11.y;
                } else if (wn == 1) {
                    float2 h0 = *(const float2*)(smH + k16 + qc);
                    float2 h1 = *(const float2*)(smH + k16 + qc + 8);
                    cs += (v00.x + v10.x) * h0.x + (v00.y + v10.y) * h0.y
                        + (v01.x + v11.x) * h1.x + (v01.y + v11.y) * h1.y;
                }
                a[f][0] = packbf(v00.x, v00.y);
                a[f][1] = packbf(v10.x, v10.y);
                a[f][2] = packbf(v01.x, v01.y);
                a[f][3] = packbf(v11.x, v11.y);
            }
            #pragma unroll
            for (int t = 0; t < 4; t++) {
                const int n = wn * 32 + t * 8 + qr;
                uint32_t b0 = *(const uint32_t*)(smB + n * B_STRIDE + (k16 + qc) * 2);
                uint32_t b1 = *(const uint32_t*)(smB + n * B_STRIDE + (k16 + qc + 8) * 2);
                #pragma unroll
                for (int f = 0; f < 2; f++) {
                    asm volatile(
                        "mma.sync.aligned.m16n8k16.row.col.f32.bf16.bf16.f32 "
                        "{%0,%1,%2,%3}, {%4,%5,%6,%7}, {%8,%9}, {%0,%1,%2,%3};\n"
                        : "+f"(acc[f][t][0]), "+f"(acc[f][t][1]),
                          "+f"(acc[f][t][2]), "+f"(acc[f][t][3])
                        : "r"(a[f][0]), "r"(a[f][1]), "r"(a[f][2]), "r"(a[f][3]),
                          "r"(b0), "r"(b1));
                }
            }
        }
        __syncthreads();
    }

    // ---- epilogue: weighted reduction ----
    float tsum = (wn == 1) ? cs : 0.f;
    #pragma unroll
    for (int f = 0; f < 2; f++) {
        #pragma unroll
        for (int rr = 0; rr < 2; rr++) {
            const int i = i0 + wm * 32 + f * 16 + qr + rr * 8;
            const float* Hrow = H + ((size_t)(b * Nn + i)) * Dd;
            if (wn == 0) tsum += rs[f][rr] * g_hsq[b * Nn + i];
            #pragma unroll
            for (int t = 0; t < 4; t++) {
                const int d0 = wn * 32 + t * 8 + qc;
                float2 hw = *(const float2*)(Hrow + d0);
                tsum += -2.f * (acc[f][t][rr * 2 + 0] * hw.x +
                                acc[f][t][rr * 2 + 1] * hw.y);
            }
        }
    }
    #pragma unroll
    for (int o = 16; o; o >>= 1) tsum += __shfl_xor_sync(0xFFFFFFFFu, tsum, o);
    if (lane == 0) s_red[wid] = tsum;
    __syncthreads();
    if (tid == 0) {
        float bs = 0.f;
        #pragma unroll
        for (int x = 0; x < 16; x++) bs += s_red[x];
        g_part[(b * (Nn / TM) + mt) * KSPLIT + ks] = bs;
        __threadfence();
        int c = atomicAdd(&g_done, 1);
        s_last = (c == NBLK - 1);
    }
    __syncthreads();

    // ---- last CTA: deterministic fixed-order final reduction ----
    if (s_last) {
        float* s = (float*)smem;
        __threadfence();
        if (tid < NBLK) s[tid] = *((volatile float*)&g_part[tid]);
        __syncthreads();
        #pragma unroll
        for (int o = NBLK / 2; o; o >>= 1) {
            if (tid < o) s[tid] += s[tid + o];
            __syncthreads();
        }
        if (tid == 0) out[0] = s[0] / (float)(Bq * Nn);
    }
}

// ---------------------------------------------------------------------------
extern "C" void kernel_launch(void* const* d_in, const int* in_sizes, int n_in,
                              void* d_out, int out_size) {
    const float* adj = (const float*)d_in[0];
    const float* emb = (const float*)d_in[1];

    static bool attr_done = false;
    if (!attr_done) {
        cudaFuncSetAttribute(k_main, cudaFuncAttributeMaxDynamicSharedMemorySize,
                             SMEM_BYTES);
        attr_done = true;
    }

    dim3 gp(Nn / 32, Bq);
    k_prep<<<gp, 256>>>(emb);
    dim3 gm(KSPLIT, Nn / TM, Bq);
    k_main<<<gm, NTHR, SMEM_BYTES>>>(adj, emb, (float*)d_out);
}

// round 14
// speedup vs baseline: 1.5865x; 1.5865x over previous
#include <cuda_runtime.h>
#include <cuda.h>
#include <cuda_bf16.h>
#include <cstdint>

#define Bq 8
#define Nn 2048
#define Dd 128
#define DE 144            // 128 emb + hsq + ones + 14 pad -> 18 n8-tiles
#define TM 128
#define TK 32
#define BOX0 40           // TMA box inner dim: 40 elems -> row pitch 160B/80B
#define NS 3
#define KSPLIT 2
#define NBLK (Bq * (Nn / TM) * KSPLIT)   // 256

#define A_STRIDE 160      // = BOX0 * 4 (fp32)
#define B_STRIDE 80       // = BOX0 * 2 (bf16)
#define A_STAGE  (TM * A_STRIDE)          // 20480 (=160*128, 128-aligned)
#define B_STAGE  (DE * B_STRIDE)          // 11520
#define STAGE_BYTES (A_STAGE + B_STAGE)   // 32000 (=250*128, 128-aligned)
#define SMEM_BYTES  (NS * STAGE_BYTES + 128)   // +128 pad for base round-up

// scratch (no allocation allowed -> device globals)
__device__ float                         g_hsq[Bq * Nn];
__device__ __align__(1024) __nv_bfloat16 g_HextT[(size_t)Bq * DE * Nn]; // [b][d][j]
__device__ float                         g_part[NBLK];
__device__ int                           g_done;

__device__ __forceinline__ uint32_t smem_u32(const void* p) {
    uint32_t a;
    asm("{ .reg .u64 t; cvta.to.shared.u64 t, %1; cvt.u32.u64 %0, t; }"
        : "=r"(a) : "l"(p));
    return a;
}
__device__ __forceinline__ uint32_t packbf(float x, float y) {
    __nv_bfloat162 p = __floats2bfloat162_rn(x, y);
    return *reinterpret_cast<uint32_t*>(&p);
}
__device__ __forceinline__ void mbar_init(uint32_t a, uint32_t cnt) {
    asm volatile("mbarrier.init.shared.b64 [%0], %1;" :: "r"(a), "r"(cnt) : "memory");
}
__device__ __forceinline__ void mbar_expect_tx(uint32_t a, uint32_t bytes) {
    asm volatile("mbarrier.arrive.expect_tx.shared.b64 _, [%0], %1;"
                 :: "r"(a), "r"(bytes) : "memory");
}
__device__ __forceinline__ void mbar_wait(uint32_t a, uint32_t parity) {
    asm volatile("{\n\t.reg .pred P;\n\t"
                 "W_%=:\n\t"
                 "mbarrier.try_wait.parity.acquire.cta.shared::cta.b64 P, [%0], %1, 0x989680;\n\t"
                 "@!P bra W_%=;\n\t}"
                 :: "r"(a), "r"(parity) : "memory");
}
__device__ __forceinline__ void tma_ld3d(uint32_t dst, const CUtensorMap* tm,
                                         int x, int y, int z, uint32_t mbar) {
    asm volatile("cp.async.bulk.tensor.3d.shared::cta.global.tile.mbarrier::complete_tx::bytes "
                 "[%0], [%1, {%2, %3, %4}], [%5];"
                 :: "r"(dst), "l"(tm), "r"(x), "r"(y), "r"(z), "r"(mbar) : "memory");
}

// ---------------------------------------------------------------------------
// Kernel 0 (prep, conflict-free): hsq + bf16 transposed extended embedding
//   HextT[b][d][j]:  d<128: h_jd,  d=128: hsq_j,  d=129: 1,  d>=130: 0
// ---------------------------------------------------------------------------
__global__ void k_prep(const float* __restrict__ H) {
    __shared__ float s2[32][137];
    __shared__ float hq[32];
    const int b = blockIdx.y, j0 = blockIdx.x * 32;
    const int tid = threadIdx.x;    // 256
    if (blockIdx.x == 0 && blockIdx.y == 0 && tid == 0) g_done = 0;

    #pragma unroll
    for (int c = 0; c < 4; c++) {
        int idx = tid + c * 256;
        int j = idx >> 5, d4 = (idx & 31) * 4;
        float4 v = *(const float4*)(H + ((size_t)(b * Nn + j0 + j)) * Dd + d4);
        s2[j][d4 + 0] = v.x; s2[j][d4 + 1] = v.y;
        s2[j][d4 + 2] = v.z; s2[j][d4 + 3] = v.w;
    }
    __syncthreads();

    {
        const int w = tid >> 5, l = tid & 31;
        const int j = w * 4 + (l >> 3), sub = l & 7;
        float sum = 0.f;
        #pragma unroll
        for (int m = 0; m < 16; m++) {
            float v = s2[j][sub + 8 * m];
            sum += v * v;
        }
        sum += __shfl_xor_sync(0xFFFFFFFFu, sum, 1);
        sum += __shfl_xor_sync(0xFFFFFFFFu, sum, 2);
        sum += __shfl_xor_sync(0xFFFFFFFFu, sum, 4);
        if (sub == 0) { hq[j] = sum; g_hsq[b * Nn + j0 + j] = sum; }
    }
    __syncthreads();

    for (int idx = tid; idx < DE * 8; idx += 256) {
        int d = idx >> 3, jq = (idx & 7) * 4;
        float v[4];
        #pragma unroll
        for (int r = 0; r < 4; r++) {
            int j = jq + r;
            v[r] = (d < 128) ? s2[j][d]
                 : (d == 128) ? hq[j]
                 : (d == 129) ? 1.0f : 0.0f;
        }
        uint2 p;
        p.x = packbf(v[0], v[1]);
        p.y = packbf(v[2], v[3]);
        *(uint2*)&g_HextT[((size_t)(b * DE + d)) * Nn + j0 + jq] = p;
    }
}

// ---------------------------------------------------------------------------
// Kernel 1: TMA-fed bf16 GEMM (R9 mainloop fragments unchanged).
// Grid (KSPLIT, 16, 8), 256 thr, occ 2. Warps 4(m) x 2(n).
// TMA smem dst MUST be 128B-aligned -> round dynamic base up (R12/R13 bug).
// ---------------------------------------------------------------------------
__global__ __launch_bounds__(256, 2)
void k_main(const __grid_constant__ CUtensorMap tmA,
            const __grid_constant__ CUtensorMap tmB,
            const float* __restrict__ H,
            float* __restrict__ out) {
    extern __shared__ __align__(128) char smem_raw[];
    __shared__ uint64_t s_mbar[NS];
    __shared__ float s_red[8];
    __shared__ int   s_last;
    const uint32_t sb0 = (smem_u32(smem_raw) + 127u) & ~127u;   // 128B-aligned base
    char* smem = smem_raw + (sb0 - smem_u32(smem_raw));
    const uint32_t mb0 = smem_u32(s_mbar);
    const int tid = threadIdx.x;
    const int wid = tid >> 5, lane = tid & 31;
    const int ks = blockIdx.x, mt = blockIdx.y, b = blockIdx.z;
    const int i0 = mt * TM;
    const int kbase = ks * (Nn / KSPLIT);
    const int NIT = (Nn / KSPLIT) / TK;         // 32

    const int wm = wid >> 1;          // 0..3 -> m offset 32*wm
    const int wn = wid & 1;           // 0..1 -> tiles [9*wn, 9*wn+9)
    const int qr = lane >> 2;         // 0..7
    const int qc = (lane & 3) * 2;    // 0,2,4,6

    if (tid == 0) {
        #pragma unroll
        for (int s = 0; s < NS; s++) mbar_init(mb0 + s * 8, 1);
    }
    __syncthreads();

    float acc[2][9][4];
    #pragma unroll
    for (int f = 0; f < 2; f++)
        #pragma unroll
        for (int t = 0; t < 9; t++)
            #pragma unroll
            for (int r = 0; r < 4; r++) acc[f][t][r] = 0.f;

    auto issueT = [&](int it) {
        int s = it % NS;
        uint32_t full = mb0 + s * 8;
        uint32_t sa = sb0 + s * STAGE_BYTES;
        mbar_expect_tx(full, STAGE_BYTES);
        tma_ld3d(sa, &tmA, kbase + it * TK, i0, b, full);
        tma_ld3d(sa + A_STAGE, &tmB, kbase + it * TK, 0, b, full);
    };

    // prologue
    if (tid == 0) { issueT(0); issueT(1); }

    for (int it = 0; it < NIT; it++) {
        if (tid == 0 && it + NS - 1 < NIT) issueT(it + NS - 1);
        mbar_wait(mb0 + (it % NS) * 8, (it / NS) & 1);

        const char* smA = smem + (it % NS) * STAGE_BYTES;
        const char* smB = smA + A_STAGE;

        #pragma unroll
        for (int k16 = 0; k16 < TK; k16 += 16) {
            uint32_t a[2][4];
            #pragma unroll
            for (int f = 0; f < 2; f++) {
                const char* ap = smA + (wm * 32 + f * 16 + qr) * A_STRIDE;
                float2 v00 = *(const float2*)(ap + (k16 + qc) * 4);
                float2 v10 = *(const float2*)(ap + 8 * A_STRIDE + (k16 + qc) * 4);
                float2 v01 = *(const float2*)(ap + (k16 + qc + 8) * 4);
                float2 v11 = *(const float2*)(ap + 8 * A_STRIDE + (k16 + qc + 8) * 4);
                a[f][0] = packbf(v00.x, v00.y);
                a[f][1] = packbf(v10.x, v10.y);
                a[f][2] = packbf(v01.x, v01.y);
                a[f][3] = packbf(v11.x, v11.y);
            }
            #pragma unroll
            for (int t = 0; t < 9; t++) {
                const int n = (wn * 9 + t) * 8 + qr;
                uint32_t b0 = *(const uint32_t*)(smB + n * B_STRIDE + (k16 + qc) * 2);
                uint32_t b1 = *(const uint32_t*)(smB + n * B_STRIDE + (k16 + qc + 8) * 2);
                #pragma unroll
                for (int f = 0; f < 2; f++) {
                    asm volatile(
                        "mma.sync.aligned.m16n8k16.row.col.f32.bf16.bf16.f32 "
                        "{%0,%1,%2,%3}, {%4,%5,%6,%7}, {%8,%9}, {%0,%1,%2,%3};\n"
                        : "+f"(acc[f][t][0]), "+f"(acc[f][t][1]),
                          "+f"(acc[f][t][2]), "+f"(acc[f][t][3])
                        : "r"(a[f][0]), "r"(a[f][1]), "r"(a[f][2]), "r"(a[f][3]),
                          "r"(b0), "r"(b1));
                }
            }
        }
        __syncthreads();   // all warps done with slot before it is overwritten
    }

    // ---- epilogue: weighted reduction ----
    float tsum = 0.f;
    #pragma unroll
    for (int f = 0; f < 2; f++) {
        #pragma unroll
        for (int rr = 0; rr < 2; rr++) {
            const int i = i0 + wm * 32 + f * 16 + qr + rr * 8;
            const float* Hrow = H + ((size_t)(b * Nn + i)) * Dd;
            const float hsq_i = g_hsq[b * Nn + i];
            #pragma unroll
            for (int t = 0; t < 9; t++) {
                const int d0 = (wn * 9 + t) * 8 + qc;
                float c0 = acc[f][t][rr * 2 + 0];
                float c1 = acc[f][t][rr * 2 + 1];
                float w0, w1;
                if (d0 < 128)       { w0 = -2.f * Hrow[d0]; w1 = -2.f * Hrow[d0 + 1]; }
                else if (d0 == 128) { w0 = 1.f;             w1 = hsq_i; }
                else                { w0 = 0.f;             w1 = 0.f; }
                tsum += c0 * w0 + c1 * w1;
            }
        }
    }
    #pragma unroll
    for (int o = 16; o; o >>= 1) tsum += __shfl_xor_sync(0xFFFFFFFFu, tsum, o);
    if (lane == 0) s_red[wid] = tsum;
    __syncthreads();
    if (tid == 0) {
        float bs = 0.f;
        #pragma unroll
        for (int x = 0; x < 8; x++) bs += s_red[x];
        g_part[(b * (Nn / TM) + mt) * KSPLIT + ks] = bs;
        __threadfence();
        int c = atomicAdd(&g_done, 1);
        s_last = (c == NBLK - 1);
    }
    __syncthreads();

    // ---- last CTA: deterministic fixed-order final reduction ----
    if (s_last) {
        float* s = (float*)smem;
        __threadfence();
        s[tid] = *((volatile float*)&g_part[tid]);
        __syncthreads();
        #pragma unroll
        for (int o = NBLK / 2; o; o >>= 1) {
            if (tid < o) s[tid] += s[tid + o];
            __syncthreads();
        }
        if (tid == 0) out[0] = s[0] / (float)(Bq * Nn);
    }
}

// ---------------------------------------------------------------------------
typedef CUresult (*EncodeFn)(CUtensorMap*, CUtensorMapDataType, cuuint32_t, void*,
                             const cuuint64_t*, const cuuint64_t*, const cuuint32_t*,
                             const cuuint32_t*, CUtensorMapInterleave, CUtensorMapSwizzle,
                             CUtensorMapL2promotion, CUtensorMapFloatOOBfill);

extern "C" void kernel_launch(void* const* d_in, const int* in_sizes, int n_in,
                              void* d_out, int out_size) {
    const float* adj = (const float*)d_in[0];
    const float* emb = (const float*)d_in[1];

    EncodeFn encode = nullptr;
    cudaDriverEntryPointQueryResult qres;
    cudaGetDriverEntryPointByVersion("cuTensorMapEncodeTiled", (void**)&encode,
                                     12000, cudaEnableDefault, &qres);

    void* hextPtr = nullptr;
    cudaGetSymbolAddress(&hextPtr, g_HextT);

    CUtensorMap tmA{}, tmB{};
    {
        cuuint64_t dims[3]    = {Nn, Nn, Bq};
        cuuint64_t strides[2] = {(cuuint64_t)Nn * 4, (cuuint64_t)Nn * Nn * 4};
        cuuint32_t box[3]     = {BOX0, TM, 1};
        cuuint32_t es[3]      = {1, 1, 1};
        encode(&tmA, CU_TENSOR_MAP_DATA_TYPE_FLOAT32, 3, (void*)adj,
               dims, strides, box, es,
               CU_TENSOR_MAP_INTERLEAVE_NONE, CU_TENSOR_MAP_SWIZZLE_NONE,
               CU_TENSOR_MAP_L2_PROMOTION_L2_128B, CU_TENSOR_MAP_FLOAT_OOB_FILL_NONE);
    }
    {
        cuuint64_t dims[3]    = {Nn, DE, Bq};
        cuuint64_t strides[2] = {(cuuint64_t)Nn * 2, (cuuint64_t)DE * Nn * 2};
        cuuint32_t box[3]     = {BOX0, DE, 1};
        cuuint32_t es[3]      = {1, 1, 1};
        encode(&tmB, CU_TENSOR_MAP_DATA_TYPE_BFLOAT16, 3, hextPtr,
               dims, strides, box, es,
               CU_TENSOR_MAP_INTERLEAVE_NONE, CU_TENSOR_MAP_SWIZZLE_NONE,
               CU_TENSOR_MAP_L2_PROMOTION_L2_128B, CU_TENSOR_MAP_FLOAT_OOB_FILL_NONE);
    }

    static bool attr_done = false;
    if (!attr_done) {
        cudaFuncSetAttribute(k_main, cudaFuncAttributeMaxDynamicSharedMemorySize,
                             SMEM_BYTES);
        attr_done = true;
    }

    dim3 gp(Nn / 32, Bq);
    k_prep<<<gp, 256>>>(emb);
    dim3 gm(KSPLIT, Nn / TM, Bq);
    k_main<<<gm, 256, SMEM_BYTES>>>(tmA, tmB, emb, (float*)d_out);
}